// round 10
// baseline (speedup 1.0000x reference)
#include <cuda_runtime.h>
#include <cuda_bf16.h>
#include <cuda_fp16.h>
#include <mma.h>
#include <math.h>
#include <stddef.h>
#include <stdint.h>

using namespace nvcuda;
typedef unsigned long long ull;

#define BATCH 512
#define TT    256
#define IIN   64
#define HH    256
#define BB    4
#define NBLK  (BATCH / BB)          // 128 recurrence CTAs
#define MTOT  (BATCH * TT)          // 131072 rows for x_proj GEMMs

// GEMM staging
#define LDT        72               // padded smem ld (bf16 elems)
#define GEMM_SMEM  (4 * 128 * LDT * 2)      // 73728 B

// Recurrence: weight stream stage [2 buf][8 k][512 tid][16 B] + packed spart
#define WST_BYTES   (2 * 8 * 512 * 16)      // 131072 B
#define SPART_BYTES (24 * 128 * 16)         // 49152 B (diagonal-free)
#define REC_DYN     (WST_BYTES + SPART_BYTES)

// ---------------- static device scratch ------------------------------------
__device__ __nv_bfloat16 g_xhi[(size_t)MTOT * IIN];
__device__ __nv_bfloat16 g_xlo[(size_t)MTOT * IIN];
__device__ __nv_bfloat16 g_w0hi[4 * HH * IIN];
__device__ __nv_bfloat16 g_w0lo[4 * HH * IIN];
__device__ __nv_bfloat16 g_w1hi[4 * HH * HH];
__device__ __nv_bfloat16 g_w1lo[4 * HH * HH];
__device__ __nv_bfloat16 g_h1hi[(size_t)MTOT * HH];
__device__ __nv_bfloat16 g_h1lo[(size_t)MTOT * HH];
__device__ float g_xp[(size_t)4 * MTOT * HH];     // [4][MTOT][256] gate-major
__device__ uint2 g_wph0[HH * HH];                 // fp16 packed w_hh [k][j]
__device__ uint2 g_wph1[HH * HH];
__device__ float g_bias0[4 * HH];
__device__ float g_bias1[4 * HH];
__device__ float g_h2last[BATCH * HH];

// ---------------- packed f32x2 helpers (Blackwell FFMA2) --------------------
#define FMA2(acc, w, x) \
    asm("fma.rn.f32x2 %0, %1, %2, %0;" : "+l"(acc) : "l"(w), "l"(x))
#define ADD2(acc, v) \
    asm("add.rn.f32x2 %0, %0, %1;" : "+l"(acc) : "l"(v))

__device__ __forceinline__ float sig_fast(float x) {
    return __fdividef(1.0f, 1.0f + __expf(-x));
}
__device__ __forceinline__ float tanh_fast(float x) {
    return __fdividef(2.0f, 1.0f + __expf(-2.0f * x)) - 1.0f;
}

// ---------------- conversions & packing ------------------------------------
__global__ void cvt_pair_kernel(const float* __restrict__ src,
                                __nv_bfloat16* __restrict__ hi,
                                __nv_bfloat16* __restrict__ lo, size_t n)
{
    for (size_t i = (size_t)blockIdx.x * blockDim.x + threadIdx.x; i < n;
         i += (size_t)gridDim.x * blockDim.x) {
        float v = src[i];
        __nv_bfloat16 h = __float2bfloat16(v);
        hi[i] = h;
        lo[i] = __float2bfloat16(v - __bfloat162float(h));
    }
}

// w_hh [4H,H] fp32 -> wph[k][j] = { half2(wi,wf), half2(wg,wo) }
__global__ void pack_whh_f16(const float* __restrict__ w_hh,
                             const float* __restrict__ b_ih,
                             const float* __restrict__ b_hh,
                             uint2* __restrict__ wp,
                             float* __restrict__ bp)
{
    for (int idx = blockIdx.x * blockDim.x + threadIdx.x; idx < HH * HH;
         idx += gridDim.x * blockDim.x) {
        int j = idx & (HH - 1);
        int k = idx >> 8;
        float wi = w_hh[(size_t)(0 * HH + j) * HH + k];
        float wf = w_hh[(size_t)(1 * HH + j) * HH + k];
        float wg = w_hh[(size_t)(2 * HH + j) * HH + k];
        float wo = w_hh[(size_t)(3 * HH + j) * HH + k];
        __half2 hif = __floats2half2_rn(wi, wf);
        __half2 hgo = __floats2half2_rn(wg, wo);
        uint2 o;
        o.x = *(uint32_t*)&hif;
        o.y = *(uint32_t*)&hgo;
        wp[k * HH + j] = o;
    }
    for (int r = blockIdx.x * blockDim.x + threadIdx.x; r < 4 * HH;
         r += gridDim.x * blockDim.x)
        bp[r] = b_ih[r] + b_hh[r];
}

// ---------------- x_proj GEMM: smem-staged HMMA (bf16 hi/lo 3-term) ----------
template <int K>
__global__ __launch_bounds__(256, 1)
void gemm_xproj_smem(const __nv_bfloat16* __restrict__ Ahi,
                     const __nv_bfloat16* __restrict__ Alo,
                     const __nv_bfloat16* __restrict__ Bhi,
                     const __nv_bfloat16* __restrict__ Blo,
                     float* __restrict__ xp)
{
    extern __shared__ __align__(16) __nv_bfloat16 sm[];
    __nv_bfloat16* sAhi = sm;
    __nv_bfloat16* sAlo = sm + 128 * LDT;
    __nv_bfloat16* sBhi = sm + 2 * 128 * LDT;
    __nv_bfloat16* sBlo = sm + 3 * 128 * LDT;

    const int tid = threadIdx.x;
    const int w   = tid >> 5;
    const int wm  = w & 3, wn = w >> 2;
    const size_t mBase = (size_t)blockIdx.x * 128;
    const int    nBase = blockIdx.y * 128;

    wmma::fragment<wmma::accumulator, 16, 16, 16, float> acc[2][4];
#pragma unroll
    for (int i = 0; i < 2; ++i)
#pragma unroll
        for (int f = 0; f < 4; ++f) wmma::fill_fragment(acc[i][f], 0.0f);

    for (int kc = 0; kc < K; kc += 64) {
        if (kc) __syncthreads();
        for (int i = tid; i < 1024; i += 256) {
            int row = i >> 3;
            int col = (i & 7) * 8;
            size_t ga = (mBase + row) * K + kc + col;
            size_t gb = ((size_t)(nBase + row)) * K + kc + col;
            *(uint4*)(sAhi + row * LDT + col) = *(const uint4*)(Ahi + ga);
            *(uint4*)(sAlo + row * LDT + col) = *(const uint4*)(Alo + ga);
            *(uint4*)(sBhi + row * LDT + col) = *(const uint4*)(Bhi + gb);
            *(uint4*)(sBlo + row * LDT + col) = *(const uint4*)(Blo + gb);
        }
        __syncthreads();

#pragma unroll
        for (int term = 0; term < 3; ++term) {
            const __nv_bfloat16* A = (term == 1) ? sAlo : sAhi;
            const __nv_bfloat16* B = (term == 2) ? sBlo : sBhi;
#pragma unroll
            for (int k0 = 0; k0 < 64; k0 += 16) {
                wmma::fragment<wmma::matrix_a, 16, 16, 16, __nv_bfloat16,
                               wmma::row_major> fa[2];
                wmma::load_matrix_sync(fa[0], A + (wm * 32) * LDT + k0, LDT);
                wmma::load_matrix_sync(fa[1], A + (wm * 32 + 16) * LDT + k0, LDT);
#pragma unroll
                for (int f = 0; f < 4; ++f) {
                    wmma::fragment<wmma::matrix_b, 16, 16, 16, __nv_bfloat16,
                                   wmma::col_major> fb;
                    wmma::load_matrix_sync(fb, B + (wn * 64 + f * 16) * LDT + k0,
                                           LDT);
                    wmma::mma_sync(acc[0][f], fa[0], fb, acc[0][f]);
                    wmma::mma_sync(acc[1][f], fa[1], fb, acc[1][f]);
                }
            }
        }
    }

    const size_t m0 = mBase + wm * 32;
    const int    n0 = nBase + wn * 64;
#pragma unroll
    for (int i = 0; i < 2; ++i)
#pragma unroll
        for (int f = 0; f < 4; ++f) {
            int c0 = n0 + f * 16;
            int g = c0 >> 8, j0 = c0 & 255;
            float* dst = xp + ((size_t)g * MTOT + m0 + i * 16) * HH + j0;
            wmma::store_matrix_sync(dst, acc[i][f], HH, wmma::mem_row_major);
        }
}

// ---------------- recurrence: cp.async-pipelined weights, FFMA2 --------------
// 512 threads = 128 j-pairs x 4 K-quarters. Weights stream through a 2x64KB
// smem stage via cp.async (no registers held -> chunk-deep MLP); each thread
// consumes only its own staged data so no barriers are needed for the stage.
// Chunk 0's prefetch for step t+1 is issued at c==7, hiding in the epilogue.
#define DOT_K(WV)                                                              \
    do {                                                                       \
        float2 f0 = __half22float2(*(const __half2*)&(WV).x);                  \
        float2 g0 = __half22float2(*(const __half2*)&(WV).y);                  \
        float2 f1 = __half22float2(*(const __half2*)&(WV).z);                  \
        float2 g1 = __half22float2(*(const __half2*)&(WV).w);                  \
        ull wif0 = *(ull*)&f0, wgo0 = *(ull*)&g0;                              \
        ull wif1 = *(ull*)&f1, wgo1 = *(ull*)&g1;                              \
        ulonglong2 h01 = *(const ulonglong2*)&shd[k * 4];                      \
        ulonglong2 h23 = *(const ulonglong2*)&shd[k * 4 + 2];                  \
        FMA2(aif0[0], wif0, h01.x); FMA2(aif0[1], wif0, h01.y);                \
        FMA2(aif0[2], wif0, h23.x); FMA2(aif0[3], wif0, h23.y);                \
        FMA2(ago0[0], wgo0, h01.x); FMA2(ago0[1], wgo0, h01.y);                \
        FMA2(ago0[2], wgo0, h23.x); FMA2(ago0[3], wgo0, h23.y);                \
        FMA2(aif1[0], wif1, h01.x); FMA2(aif1[1], wif1, h01.y);                \
        FMA2(aif1[2], wif1, h23.x); FMA2(aif1[3], wif1, h23.y);                \
        FMA2(ago1[0], wgo1, h01.x); FMA2(ago1[1], wgo1, h01.y);                \
        FMA2(ago1[2], wgo1, h23.x); FMA2(ago1[3], wgo1, h23.y);                \
    } while (0)

#define PREFETCH_CHUNK(c_, buf_)                                               \
    do {                                                                       \
        _Pragma("unroll")                                                      \
        for (int kk = 0; kk < 8; ++kk) {                                       \
            uint32_t dst = wst_u32 + (((buf_) * 8 + kk) * 512) * 16 + my_off;  \
            const void* src =                                                  \
                (const void*)(wph + (size_t)(kbase + (c_) * 8 + kk) * HH + j0);\
            asm volatile("cp.async.cg.shared.global [%0], [%1], 16;"           \
                         :: "r"(dst), "l"(src));                               \
        }                                                                      \
        asm volatile("cp.async.commit_group;" ::: "memory");                   \
    } while (0)

template <bool STORE_PAIR>
__global__ __launch_bounds__(512, 1)
void lstm_rec_kernel(const float* __restrict__ xp,   // [4][MTOT][256]
                     const uint2* __restrict__ wph,  // [256][256]
                     const float* __restrict__ bp,   // [4*256]
                     __nv_bfloat16* __restrict__ ohi,
                     __nv_bfloat16* __restrict__ olo,
                     float* __restrict__ olast)      // [BATCH][HH]
{
    extern __shared__ __align__(16) char dsm[];
    char*       wst   = dsm;                              // [2][8][512][16B]
    ulonglong2* spart = (ulonglong2*)(dsm + WST_BYTES);   // [24][128]
    __shared__ __align__(16) ull shd[HH * BB];            // [k][b] {h,h}

    const int tid = threadIdx.x;
    const int jp  = tid & 127;
    const int q   = tid >> 7;                 // K-quarter, also finalized batch
    const int j0  = jp * 2;
    const int b0  = blockIdx.x * BB;
    const int bq  = b0 + q;
    const int kbase = q * 64;

    uint32_t wst_u32;
    asm("{ .reg .u64 t; cvta.to.shared.u64 t, %1; cvt.u32.u64 %0, t; }"
        : "=r"(wst_u32) : "l"(wst));
    const uint32_t my_off = tid * 16;

    float bias[2][4];
#pragma unroll
    for (int jj = 0; jj < 2; ++jj)
#pragma unroll
        for (int g = 0; g < 4; ++g)
            bias[jj][g] = bp[g * HH + j0 + jj];

    float c2[2] = {0.0f, 0.0f};

    for (int i = tid; i < HH * BB; i += 512) shd[i] = 0ull;
    __syncthreads();

    PREFETCH_CHUNK(0, 0);                     // prime the pipeline

    for (int t = 0; t < TT; ++t) {
        const size_t m = (size_t)bq * TT + t;
        float xg[2][4];
#pragma unroll
        for (int g = 0; g < 4; ++g) {
            float2 v = *(const float2*)&xp[((size_t)g * MTOT + m) * HH + j0];
            xg[0][g] = v.x;
            xg[1][g] = v.y;
        }

        ull aif0[4], ago0[4], aif1[4], ago1[4];
#pragma unroll
        for (int b = 0; b < 4; ++b) {
            aif0[b] = 0ull; ago0[b] = 0ull; aif1[b] = 0ull; ago1[b] = 0ull;
        }

#pragma unroll
        for (int c = 0; c < 8; ++c) {
            const int nc   = (c + 1) & 7;     // c==7 -> chunk 0 for next step
            const int nbuf = (c + 1) & 1;
            PREFETCH_CHUNK(nc, nbuf);
            asm volatile("cp.async.wait_group 1;" ::: "memory");
#pragma unroll
            for (int kk = 0; kk < 8; ++kk) {
                uint4 wv = *(const uint4*)(wst + (((c & 1) * 8 + kk) * 512) * 16
                                           + my_off);
                const int k = kbase + c * 8 + kk;
                DOT_K(wv);
            }
        }

        // export partials (diagonal-free packing)
#pragma unroll
        for (int b = 0; b < 4; ++b) {
            if (b != q) {
                const int bidx = b > q ? b - 1 : b;
                spart[((q * 3 + bidx) * 2 + 0) * 128 + jp] =
                    make_ulonglong2(aif0[b], aif1[b]);
                spart[((q * 3 + bidx) * 2 + 1) * 128 + jp] =
                    make_ulonglong2(ago0[b], ago1[b]);
            }
        }
        __syncthreads();

        // finalize batch q for j0, j0+1
        ull vif[2] = {aif0[q], aif1[q]};
        ull vgo[2] = {ago0[q], ago1[q]};
#pragma unroll
        for (int qq = 0; qq < 4; ++qq) {
            if (qq != q) {
                const int bidx = q > qq ? q - 1 : q;
                ulonglong2 p0 = spart[((qq * 3 + bidx) * 2 + 0) * 128 + jp];
                ulonglong2 p1 = spart[((qq * 3 + bidx) * 2 + 1) * 128 + jp];
                ADD2(vif[0], p0.x); ADD2(vif[1], p0.y);
                ADD2(vgo[0], p1.x); ADD2(vgo[1], p1.y);
            }
        }

        float hv[2];
#pragma unroll
        for (int jj = 0; jj < 2; ++jj) {
            float vi, vf, vg, vo;
            asm("mov.b64 {%0,%1}, %2;" : "=f"(vi), "=f"(vf) : "l"(vif[jj]));
            asm("mov.b64 {%0,%1}, %2;" : "=f"(vg), "=f"(vo) : "l"(vgo[jj]));
            vi += bias[jj][0] + xg[jj][0];
            vf += bias[jj][1] + xg[jj][1];
            vg += bias[jj][2] + xg[jj][2];
            vo += bias[jj][3] + xg[jj][3];
            float iv = sig_fast(vi);
            float fv = sig_fast(vf);
            float gv = tanh_fast(vg);
            float ov = sig_fast(vo);
            c2[jj] = fv * c2[jj] + iv * gv;
            hv[jj] = ov * tanh_fast(c2[jj]);
            ull hd;
            asm("mov.b64 %0, {%1,%1};" : "=l"(hd) : "f"(hv[jj]));
            shd[(j0 + jj) * 4 + q] = hd;
        }

        if (STORE_PAIR) {
            __nv_bfloat162 h2 = __float22bfloat162_rn(make_float2(hv[0], hv[1]));
            float l0 = hv[0] - __bfloat162float(__low2bfloat16(h2));
            float l1 = hv[1] - __bfloat162float(__high2bfloat16(h2));
            __nv_bfloat162 l2 = __float22bfloat162_rn(make_float2(l0, l1));
            *(uint32_t*)&ohi[m * HH + j0] = *(uint32_t*)&h2;
            *(uint32_t*)&olo[m * HH + j0] = *(uint32_t*)&l2;
        } else if (t == TT - 1) {
            *(float2*)&olast[(size_t)bq * HH + j0] = make_float2(hv[0], hv[1]);
        }
        __syncthreads();
    }
}

// ---------------- LayerNorm + exact GELU + linear head ----------------------
__device__ __forceinline__ float block_sum_256(float v, float* red)
{
    __syncthreads();
#pragma unroll
    for (int o = 16; o > 0; o >>= 1) v += __shfl_down_sync(0xffffffffu, v, o);
    if ((threadIdx.x & 31) == 0) red[threadIdx.x >> 5] = v;
    __syncthreads();
    if (threadIdx.x < 8) {
        v = red[threadIdx.x];
#pragma unroll
        for (int o = 4; o > 0; o >>= 1) v += __shfl_down_sync(0xffu, v, o);
        if (threadIdx.x == 0) red[0] = v;
    }
    __syncthreads();
    return red[0];
}

__global__ __launch_bounds__(HH)
void head_kernel(const float* __restrict__ h2,
                 const float* __restrict__ gamma,
                 const float* __restrict__ beta,
                 const float* __restrict__ hw,
                 const float* __restrict__ hb,
                 float* __restrict__ outp)
{
    __shared__ float red[8];
    const int b = blockIdx.x;
    const int tid = threadIdx.x;

    float v  = h2[(size_t)b * HH + tid];
    float mu = block_sum_256(v, red) * (1.0f / HH);
    float d  = v - mu;
    float var = block_sum_256(d * d, red) * (1.0f / HH);
    float y  = d * rsqrtf(var + 1e-5f) * gamma[tid] + beta[tid];
    float gl = 0.5f * y * (1.0f + erff(y * 0.70710678118654752440f));
    float s  = block_sum_256(gl * hw[tid], red);
    if (tid == 0) outp[b] = s + hb[0];
}

// ---------------- launch ----------------------------------------------------
extern "C" void kernel_launch(void* const* d_in, const int* in_sizes, int n_in,
                              void* d_out, int out_size)
{
    (void)in_sizes; (void)n_in; (void)out_size;

    const float* x     = (const float*)d_in[0];
    const float* w_ih0 = (const float*)d_in[1];
    const float* w_hh0 = (const float*)d_in[2];
    const float* b_ih0 = (const float*)d_in[3];
    const float* b_hh0 = (const float*)d_in[4];
    const float* w_ih1 = (const float*)d_in[5];
    const float* w_hh1 = (const float*)d_in[6];
    const float* b_ih1 = (const float*)d_in[7];
    const float* b_hh1 = (const float*)d_in[8];
    const float* ln_g  = (const float*)d_in[9];
    const float* ln_b  = (const float*)d_in[10];
    const float* hw    = (const float*)d_in[11];
    const float* hb    = (const float*)d_in[12];
    float* outp = (float*)d_out;

    __nv_bfloat16 *xhi, *xlo, *w0hi, *w0lo, *w1hi, *w1lo, *h1hi, *h1lo;
    uint2 *wph0, *wph1;
    float *xp, *bp0, *bp1, *h2l;
    cudaGetSymbolAddress((void**)&xhi,  g_xhi);
    cudaGetSymbolAddress((void**)&xlo,  g_xlo);
    cudaGetSymbolAddress((void**)&w0hi, g_w0hi);
    cudaGetSymbolAddress((void**)&w0lo, g_w0lo);
    cudaGetSymbolAddress((void**)&w1hi, g_w1hi);
    cudaGetSymbolAddress((void**)&w1lo, g_w1lo);
    cudaGetSymbolAddress((void**)&h1hi, g_h1hi);
    cudaGetSymbolAddress((void**)&h1lo, g_h1lo);
    cudaGetSymbolAddress((void**)&xp,   g_xp);
    cudaGetSymbolAddress((void**)&wph0, g_wph0);
    cudaGetSymbolAddress((void**)&wph1, g_wph1);
    cudaGetSymbolAddress((void**)&bp0,  g_bias0);
    cudaGetSymbolAddress((void**)&bp1,  g_bias1);
    cudaGetSymbolAddress((void**)&h2l,  g_h2last);

    cudaFuncSetAttribute(gemm_xproj_smem<IIN>,
                         cudaFuncAttributeMaxDynamicSharedMemorySize, GEMM_SMEM);
    cudaFuncSetAttribute(gemm_xproj_smem<HH>,
                         cudaFuncAttributeMaxDynamicSharedMemorySize, GEMM_SMEM);
    cudaFuncSetAttribute(lstm_rec_kernel<true>,
                         cudaFuncAttributeMaxDynamicSharedMemorySize, REC_DYN);
    cudaFuncSetAttribute(lstm_rec_kernel<false>,
                         cudaFuncAttributeMaxDynamicSharedMemorySize, REC_DYN);

    // Launch order puts lstm_rec_kernel<true> 6th (ncu -s 5 -c 1 profiles it).
    cvt_pair_kernel<<<512, 256>>>(x,     xhi,  xlo,  (size_t)MTOT * IIN);
    cvt_pair_kernel<<<128, 256>>>(w_ih0, w0hi, w0lo, (size_t)4 * HH * IIN);
    pack_whh_f16<<<128, 256>>>(w_hh0, b_ih0, b_hh0, wph0, bp0);
    pack_whh_f16<<<128, 256>>>(w_hh1, b_ih1, b_hh1, wph1, bp1);

    // layer 0
    gemm_xproj_smem<IIN><<<dim3(MTOT / 128, 8), 256, GEMM_SMEM>>>(
        xhi, xlo, w0hi, w0lo, xp);
    lstm_rec_kernel<true><<<NBLK, 512, REC_DYN>>>(xp, wph0, bp0,
                                                  h1hi, h1lo, nullptr);

    // layer 1
    cvt_pair_kernel<<<256, 256>>>(w_ih1, w1hi, w1lo, (size_t)4 * HH * HH);
    gemm_xproj_smem<HH><<<dim3(MTOT / 128, 8), 256, GEMM_SMEM>>>(
        h1hi, h1lo, w1hi, w1lo, xp);
    lstm_rec_kernel<false><<<NBLK, 512, REC_DYN>>>(xp, wph1, bp1,
                                                   nullptr, nullptr, h2l);

    head_kernel<<<BATCH, HH>>>(h2l, ln_g, ln_b, hw, hb, outp);
}

// round 11
// speedup vs baseline: 1.1442x; 1.1442x over previous
#include <cuda_runtime.h>
#include <cuda_bf16.h>
#include <cuda_fp16.h>
#include <mma.h>
#include <math.h>
#include <stddef.h>
#include <stdint.h>

using namespace nvcuda;
typedef unsigned long long ull;

#define BATCH 512
#define TT    256
#define IIN   64
#define HH    256
#define MTOT  (BATCH * TT)          // 131072 rows for x_proj GEMMs

// GEMM staging
#define LDT        72               // padded smem ld (bf16 elems)
#define GEMM_SMEM  (4 * 128 * LDT * 2)      // 73728 B

// TC recurrence: 32 CTAs x 16 batches, 512 threads (16 warps x 64 N-cols)
#define MB       16
#define NCTA     (BATCH / MB)       // 32
#define RTHR     512
// smem: stage [16 warps][2 buf][16 k][72 n] half   = 73728 B
//       A     [16 m][264 k] half                   =  8448 B
//       scr   [16 m][1044 n] f32                   = 66816 B
//       bias  [1032] f32                           =  4128 B
#define STG_BYTES   73728
#define A_OFF       STG_BYTES
#define A_BYTES     (16 * 264 * 2)
#define SCR_OFF     (A_OFF + A_BYTES)
#define SCR_BYTES   (16 * 1044 * 4)
#define BIA_OFF     (SCR_OFF + SCR_BYTES)
#define REC_SMEM    (BIA_OFF + 1032 * 4)    // 153120 B

// ---------------- static device scratch ------------------------------------
__device__ __nv_bfloat16 g_xhi[(size_t)MTOT * IIN];
__device__ __nv_bfloat16 g_xlo[(size_t)MTOT * IIN];
__device__ __nv_bfloat16 g_w0hi[4 * HH * IIN];
__device__ __nv_bfloat16 g_w0lo[4 * HH * IIN];
__device__ __nv_bfloat16 g_w1hi[4 * HH * HH];
__device__ __nv_bfloat16 g_w1lo[4 * HH * HH];
__device__ __nv_bfloat16 g_h1hi[(size_t)MTOT * HH];
__device__ __nv_bfloat16 g_h1lo[(size_t)MTOT * HH];
__device__ float  g_xp[(size_t)4 * MTOT * HH];    // [4][MTOT][256] gate-major
__device__ __half g_w2_0[HH * 4 * HH];            // k-major W^T [256][1024]
__device__ __half g_w2_1[HH * 4 * HH];
__device__ float  g_bias0[4 * HH];
__device__ float  g_bias1[4 * HH];
__device__ float  g_h2last[BATCH * HH];

__device__ __forceinline__ float tanh_ap(float x) {
    float y;
    asm("tanh.approx.f32 %0, %1;" : "=f"(y) : "f"(x));
    return y;
}
__device__ __forceinline__ float sig_ap(float x) {
    return 0.5f * tanh_ap(0.5f * x) + 0.5f;
}

// ---------------- conversions & packing ------------------------------------
__global__ void cvt_pair_kernel(const float* __restrict__ src,
                                __nv_bfloat16* __restrict__ hi,
                                __nv_bfloat16* __restrict__ lo, size_t n)
{
    for (size_t i = (size_t)blockIdx.x * blockDim.x + threadIdx.x; i < n;
         i += (size_t)gridDim.x * blockDim.x) {
        float v = src[i];
        __nv_bfloat16 h = __float2bfloat16(v);
        hi[i] = h;
        lo[i] = __float2bfloat16(v - __bfloat162float(h));
    }
}

// w_hh [1024 n][256 k] fp32 -> w2 [256 k][1024 n] fp16 (= W^T, k-major)
__global__ void pack_whh_tc(const float* __restrict__ w_hh,
                            const float* __restrict__ b_ih,
                            const float* __restrict__ b_hh,
                            __half* __restrict__ w2,
                            float* __restrict__ bp)
{
    for (int idx = blockIdx.x * blockDim.x + threadIdx.x; idx < 4 * HH * HH;
         idx += gridDim.x * blockDim.x) {
        int n = idx & 1023;
        int k = idx >> 10;
        w2[idx] = __float2half(w_hh[(size_t)n * HH + k]);
    }
    for (int r = blockIdx.x * blockDim.x + threadIdx.x; r < 4 * HH;
         r += gridDim.x * blockDim.x)
        bp[r] = b_ih[r] + b_hh[r];
}

// ---------------- x_proj GEMM: smem-staged HMMA (bf16 hi/lo 3-term) ----------
template <int K>
__global__ __launch_bounds__(256, 1)
void gemm_xproj_smem(const __nv_bfloat16* __restrict__ Ahi,
                     const __nv_bfloat16* __restrict__ Alo,
                     const __nv_bfloat16* __restrict__ Bhi,
                     const __nv_bfloat16* __restrict__ Blo,
                     float* __restrict__ xp)
{
    extern __shared__ __align__(16) __nv_bfloat16 sm[];
    __nv_bfloat16* sAhi = sm;
    __nv_bfloat16* sAlo = sm + 128 * LDT;
    __nv_bfloat16* sBhi = sm + 2 * 128 * LDT;
    __nv_bfloat16* sBlo = sm + 3 * 128 * LDT;

    const int tid = threadIdx.x;
    const int w   = tid >> 5;
    const int wm  = w & 3, wn = w >> 2;
    const size_t mBase = (size_t)blockIdx.x * 128;
    const int    nBase = blockIdx.y * 128;

    wmma::fragment<wmma::accumulator, 16, 16, 16, float> acc[2][4];
#pragma unroll
    for (int i = 0; i < 2; ++i)
#pragma unroll
        for (int f = 0; f < 4; ++f) wmma::fill_fragment(acc[i][f], 0.0f);

    for (int kc = 0; kc < K; kc += 64) {
        if (kc) __syncthreads();
        for (int i = tid; i < 1024; i += 256) {
            int row = i >> 3;
            int col = (i & 7) * 8;
            size_t ga = (mBase + row) * K + kc + col;
            size_t gb = ((size_t)(nBase + row)) * K + kc + col;
            *(uint4*)(sAhi + row * LDT + col) = *(const uint4*)(Ahi + ga);
            *(uint4*)(sAlo + row * LDT + col) = *(const uint4*)(Alo + ga);
            *(uint4*)(sBhi + row * LDT + col) = *(const uint4*)(Bhi + gb);
            *(uint4*)(sBlo + row * LDT + col) = *(const uint4*)(Blo + gb);
        }
        __syncthreads();

#pragma unroll
        for (int term = 0; term < 3; ++term) {
            const __nv_bfloat16* A = (term == 1) ? sAlo : sAhi;
            const __nv_bfloat16* B = (term == 2) ? sBlo : sBhi;
#pragma unroll
            for (int k0 = 0; k0 < 64; k0 += 16) {
                wmma::fragment<wmma::matrix_a, 16, 16, 16, __nv_bfloat16,
                               wmma::row_major> fa[2];
                wmma::load_matrix_sync(fa[0], A + (wm * 32) * LDT + k0, LDT);
                wmma::load_matrix_sync(fa[1], A + (wm * 32 + 16) * LDT + k0, LDT);
#pragma unroll
                for (int f = 0; f < 4; ++f) {
                    wmma::fragment<wmma::matrix_b, 16, 16, 16, __nv_bfloat16,
                                   wmma::col_major> fb;
                    wmma::load_matrix_sync(fb, B + (wn * 64 + f * 16) * LDT + k0,
                                           LDT);
                    wmma::mma_sync(acc[0][f], fa[0], fb, acc[0][f]);
                    wmma::mma_sync(acc[1][f], fa[1], fb, acc[1][f]);
                }
            }
        }
    }

    const size_t m0 = mBase + wm * 32;
    const int    n0 = nBase + wn * 64;
#pragma unroll
    for (int i = 0; i < 2; ++i)
#pragma unroll
        for (int f = 0; f < 4; ++f) {
            int c0 = n0 + f * 16;
            int g = c0 >> 8, j0 = c0 & 255;
            float* dst = xp + ((size_t)g * MTOT + m0 + i * 16) * HH + j0;
            wmma::store_matrix_sync(dst, acc[i][f], HH, wmma::mem_row_major);
        }
}

// ---------------- tensor-core recurrence (single CTA, no clusters) -----------
// 32 CTAs x 16 batches. Per step: gates[16,1024] = A[16,256]@W^T via wmma fp16,
// W streamed k-major through warp-private cp.async double buffers (32KB/chunk,
// 16 chunks), acc -> smem scratch -> per-thread state update -> h fp16 -> A.
template <bool STORE_PAIR>
__global__ __launch_bounds__(RTHR, 1)
void lstm_rec_tc(const float* __restrict__ xp,    // [4][MTOT][256]
                 const __half* __restrict__ w2,   // [256][1024] k-major
                 const float* __restrict__ bp,    // [1024]
                 __nv_bfloat16* __restrict__ ohi,
                 __nv_bfloat16* __restrict__ olo,
                 float* __restrict__ olast)       // [BATCH][HH]
{
    extern __shared__ __align__(16) char dsm[];
    __half* Ah    = (__half*)(dsm + A_OFF);       // [16][264]
    float*  scr   = (float*)(dsm + SCR_OFF);      // [16][1044]
    float*  sbias = (float*)(dsm + BIA_OFF);      // [1024]

    const int tid  = threadIdx.x;
    const int wid  = tid >> 5;
    const int lane = tid & 31;
    const int n0   = wid * 64;                    // warp's N-column base
    const int b    = wid;                         // epilogue batch == warp id
    const int j0e  = lane * 8;                    // epilogue j base (8 j's)
    const int b0c  = blockIdx.x * MB;

    __half* stg = (__half*)dsm + wid * 2304;      // warp-private [2][16][72]
    uint32_t stg_u32;
    asm("{ .reg .u64 t; cvta.to.shared.u64 t, %1; cvt.u32.u64 %0, t; }"
        : "=r"(stg_u32) : "l"((const void*)stg));

#define PREF_W(kc_, buf_)                                                      \
    do {                                                                       \
        _Pragma("unroll")                                                      \
        for (int ii = 0; ii < 4; ++ii) {                                       \
            int idx = ii * 32 + lane;                                          \
            int row = idx >> 3, col = (idx & 7) * 8;                           \
            uint32_t dst = stg_u32 + (buf_) * 2304 + row * 144 + col * 2;      \
            const void* src = (const void*)(w2 +                               \
                (size_t)((kc_) * 16 + row) * 1024 + n0 + col);                 \
            asm volatile("cp.async.cg.shared.global [%0], [%1], 16;"           \
                         :: "r"(dst), "l"(src));                               \
        }                                                                      \
        asm volatile("cp.async.commit_group;" ::: "memory");                   \
    } while (0)

    // init: A = 0, bias -> smem
    for (int i = tid; i < 16 * 264; i += RTHR) Ah[i] = __float2half(0.0f);
    for (int i = tid; i < 1024; i += RTHR) sbias[i] = bp[i];

    float c8[8];
#pragma unroll
    for (int v = 0; v < 8; ++v) c8[v] = 0.0f;

    PREF_W(0, 0);                                 // prime the pipeline
    __syncthreads();

    for (int t = 0; t < TT; ++t) {
        const size_t m = (size_t)(b0c + b) * TT + t;

        // prefetch xp for this thread's (b, j0e..j0e+8) — consumed after BAR_A
        float4 xg[4][2];
#pragma unroll
        for (int g = 0; g < 4; ++g) {
            const float* base = xp + ((size_t)g * MTOT + m) * HH + j0e;
            xg[g][0] = __ldg((const float4*)base);
            xg[g][1] = __ldg((const float4*)(base + 4));
        }

        // ---- MMA phase: 16 k-chunks ----
        wmma::fragment<wmma::accumulator, 16, 16, 16, float> acc[4];
#pragma unroll
        for (int f = 0; f < 4; ++f) wmma::fill_fragment(acc[f], 0.0f);

#pragma unroll 4
        for (int kc = 0; kc < 16; ++kc) {
            PREF_W((kc + 1) & 15, (kc + 1) & 1);
            asm volatile("cp.async.wait_group 1;" ::: "memory");
            __syncwarp();

            wmma::fragment<wmma::matrix_a, 16, 16, 16, __half,
                           wmma::row_major> fa;
            wmma::load_matrix_sync(fa, Ah + kc * 16, 264);
            const __half* sb = stg + (kc & 1) * 1152;
#pragma unroll
            for (int f = 0; f < 4; ++f) {
                wmma::fragment<wmma::matrix_b, 16, 16, 16, __half,
                               wmma::row_major> fb;
                wmma::load_matrix_sync(fb, sb + f * 16, 72);
                wmma::mma_sync(acc[f], fa, fb, acc[f]);
            }
        }

        // acc -> scratch
#pragma unroll
        for (int f = 0; f < 4; ++f)
            wmma::store_matrix_sync(scr + n0 + f * 16, acc[f], 1044,
                                    wmma::mem_row_major);
        __syncthreads();                          // BAR_A

        // ---- state update: thread owns (batch b, j0e..j0e+7) ----
        float G[4][8];
#pragma unroll
        for (int g = 0; g < 4; ++g) {
            const float* sp = scr + b * 1044 + g * 256 + j0e;
            float4 s0 = *(const float4*)sp;
            float4 s1 = *(const float4*)(sp + 4);
            float4 bb0 = *(const float4*)(sbias + g * 256 + j0e);
            float4 bb1 = *(const float4*)(sbias + g * 256 + j0e + 4);
            G[g][0] = s0.x + bb0.x + xg[g][0].x;
            G[g][1] = s0.y + bb0.y + xg[g][0].y;
            G[g][2] = s0.z + bb0.z + xg[g][0].z;
            G[g][3] = s0.w + bb0.w + xg[g][0].w;
            G[g][4] = s1.x + bb1.x + xg[g][1].x;
            G[g][5] = s1.y + bb1.y + xg[g][1].y;
            G[g][6] = s1.z + bb1.z + xg[g][1].z;
            G[g][7] = s1.w + bb1.w + xg[g][1].w;
        }

        float hv[8];
#pragma unroll
        for (int v = 0; v < 8; ++v) {
            float iv = sig_ap(G[0][v]);
            float fv = sig_ap(G[1][v]);
            float gv = tanh_ap(G[2][v]);
            float ov = sig_ap(G[3][v]);
            c8[v] = fv * c8[v] + iv * gv;
            hv[v] = ov * tanh_ap(c8[v]);
        }

        // h -> A smem (fp16)
        {
            __half2 p0 = __floats2half2_rn(hv[0], hv[1]);
            __half2 p1 = __floats2half2_rn(hv[2], hv[3]);
            __half2 p2 = __floats2half2_rn(hv[4], hv[5]);
            __half2 p3 = __floats2half2_rn(hv[6], hv[7]);
            uint4 pk = make_uint4(*(uint32_t*)&p0, *(uint32_t*)&p1,
                                  *(uint32_t*)&p2, *(uint32_t*)&p3);
            *(uint4*)&Ah[b * 264 + j0e] = pk;
        }

        // outputs
        if (STORE_PAIR) {
            __nv_bfloat162 h0 = __float22bfloat162_rn(make_float2(hv[0], hv[1]));
            __nv_bfloat162 h1 = __float22bfloat162_rn(make_float2(hv[2], hv[3]));
            __nv_bfloat162 h2 = __float22bfloat162_rn(make_float2(hv[4], hv[5]));
            __nv_bfloat162 h3 = __float22bfloat162_rn(make_float2(hv[6], hv[7]));
            float l[8];
            l[0] = hv[0] - __bfloat162float(__low2bfloat16(h0));
            l[1] = hv[1] - __bfloat162float(__high2bfloat16(h0));
            l[2] = hv[2] - __bfloat162float(__low2bfloat16(h1));
            l[3] = hv[3] - __bfloat162float(__high2bfloat16(h1));
            l[4] = hv[4] - __bfloat162float(__low2bfloat16(h2));
            l[5] = hv[5] - __bfloat162float(__high2bfloat16(h2));
            l[6] = hv[6] - __bfloat162float(__low2bfloat16(h3));
            l[7] = hv[7] - __bfloat162float(__high2bfloat16(h3));
            __nv_bfloat162 l0 = __float22bfloat162_rn(make_float2(l[0], l[1]));
            __nv_bfloat162 l1 = __float22bfloat162_rn(make_float2(l[2], l[3]));
            __nv_bfloat162 l2 = __float22bfloat162_rn(make_float2(l[4], l[5]));
            __nv_bfloat162 l3 = __float22bfloat162_rn(make_float2(l[6], l[7]));
            *(uint4*)&ohi[m * HH + j0e] =
                make_uint4(*(uint32_t*)&h0, *(uint32_t*)&h1,
                           *(uint32_t*)&h2, *(uint32_t*)&h3);
            *(uint4*)&olo[m * HH + j0e] =
                make_uint4(*(uint32_t*)&l0, *(uint32_t*)&l1,
                           *(uint32_t*)&l2, *(uint32_t*)&l3);
        } else if (t == TT - 1) {
            float* dst = olast + (size_t)(b0c + b) * HH + j0e;
            *(float4*)dst = make_float4(hv[0], hv[1], hv[2], hv[3]);
            *(float4*)(dst + 4) = make_float4(hv[4], hv[5], hv[6], hv[7]);
        }
        __syncthreads();                          // BAR_B
    }
#undef PREF_W
}

// ---------------- LayerNorm + exact GELU + linear head ----------------------
__device__ __forceinline__ float block_sum_256(float v, float* red)
{
    __syncthreads();
#pragma unroll
    for (int o = 16; o > 0; o >>= 1) v += __shfl_down_sync(0xffffffffu, v, o);
    if ((threadIdx.x & 31) == 0) red[threadIdx.x >> 5] = v;
    __syncthreads();
    if (threadIdx.x < 8) {
        v = red[threadIdx.x];
#pragma unroll
        for (int o = 4; o > 0; o >>= 1) v += __shfl_down_sync(0xffu, v, o);
        if (threadIdx.x == 0) red[0] = v;
    }
    __syncthreads();
    return red[0];
}

__global__ __launch_bounds__(HH)
void head_kernel(const float* __restrict__ h2,
                 const float* __restrict__ gamma,
                 const float* __restrict__ beta,
                 const float* __restrict__ hw,
                 const float* __restrict__ hb,
                 float* __restrict__ outp)
{
    __shared__ float red[8];
    const int b = blockIdx.x;
    const int tid = threadIdx.x;

    float v  = h2[(size_t)b * HH + tid];
    float mu = block_sum_256(v, red) * (1.0f / HH);
    float d  = v - mu;
    float var = block_sum_256(d * d, red) * (1.0f / HH);
    float y  = d * rsqrtf(var + 1e-5f) * gamma[tid] + beta[tid];
    float gl = 0.5f * y * (1.0f + erff(y * 0.70710678118654752440f));
    float s  = block_sum_256(gl * hw[tid], red);
    if (tid == 0) outp[b] = s + hb[0];
}

// ---------------- launch ----------------------------------------------------
extern "C" void kernel_launch(void* const* d_in, const int* in_sizes, int n_in,
                              void* d_out, int out_size)
{
    (void)in_sizes; (void)n_in; (void)out_size;

    const float* x     = (const float*)d_in[0];
    const float* w_ih0 = (const float*)d_in[1];
    const float* w_hh0 = (const float*)d_in[2];
    const float* b_ih0 = (const float*)d_in[3];
    const float* b_hh0 = (const float*)d_in[4];
    const float* w_ih1 = (const float*)d_in[5];
    const float* w_hh1 = (const float*)d_in[6];
    const float* b_ih1 = (const float*)d_in[7];
    const float* b_hh1 = (const float*)d_in[8];
    const float* ln_g  = (const float*)d_in[9];
    const float* ln_b  = (const float*)d_in[10];
    const float* hw    = (const float*)d_in[11];
    const float* hb    = (const float*)d_in[12];
    float* outp = (float*)d_out;

    __nv_bfloat16 *xhi, *xlo, *w0hi, *w0lo, *w1hi, *w1lo, *h1hi, *h1lo;
    __half *w20, *w21;
    float *xp, *bp0, *bp1, *h2l;
    cudaGetSymbolAddress((void**)&xhi,  g_xhi);
    cudaGetSymbolAddress((void**)&xlo,  g_xlo);
    cudaGetSymbolAddress((void**)&w0hi, g_w0hi);
    cudaGetSymbolAddress((void**)&w0lo, g_w0lo);
    cudaGetSymbolAddress((void**)&w1hi, g_w1hi);
    cudaGetSymbolAddress((void**)&w1lo, g_w1lo);
    cudaGetSymbolAddress((void**)&h1hi, g_h1hi);
    cudaGetSymbolAddress((void**)&h1lo, g_h1lo);
    cudaGetSymbolAddress((void**)&xp,   g_xp);
    cudaGetSymbolAddress((void**)&w20,  g_w2_0);
    cudaGetSymbolAddress((void**)&w21,  g_w2_1);
    cudaGetSymbolAddress((void**)&bp0,  g_bias0);
    cudaGetSymbolAddress((void**)&bp1,  g_bias1);
    cudaGetSymbolAddress((void**)&h2l,  g_h2last);

    cudaFuncSetAttribute(gemm_xproj_smem<IIN>,
                         cudaFuncAttributeMaxDynamicSharedMemorySize, GEMM_SMEM);
    cudaFuncSetAttribute(gemm_xproj_smem<HH>,
                         cudaFuncAttributeMaxDynamicSharedMemorySize, GEMM_SMEM);
    cudaFuncSetAttribute(lstm_rec_tc<true>,
                         cudaFuncAttributeMaxDynamicSharedMemorySize, REC_SMEM);
    cudaFuncSetAttribute(lstm_rec_tc<false>,
                         cudaFuncAttributeMaxDynamicSharedMemorySize, REC_SMEM);

    cvt_pair_kernel<<<512, 256>>>(x,     xhi,  xlo,  (size_t)MTOT * IIN);
    cvt_pair_kernel<<<128, 256>>>(w_ih0, w0hi, w0lo, (size_t)4 * HH * IIN);
    pack_whh_tc<<<256, 256>>>(w_hh0, b_ih0, b_hh0, w20, bp0);
    pack_whh_tc<<<256, 256>>>(w_hh1, b_ih1, b_hh1, w21, bp1);

    // layer 0
    gemm_xproj_smem<IIN><<<dim3(MTOT / 128, 8), 256, GEMM_SMEM>>>(
        xhi, xlo, w0hi, w0lo, xp);
    lstm_rec_tc<true><<<NCTA, RTHR, REC_SMEM>>>(xp, w20, bp0,
                                                h1hi, h1lo, nullptr);

    // layer 1
    cvt_pair_kernel<<<256, 256>>>(w_ih1, w1hi, w1lo, (size_t)4 * HH * HH);
    gemm_xproj_smem<HH><<<dim3(MTOT / 128, 8), 256, GEMM_SMEM>>>(
        h1hi, h1lo, w1hi, w1lo, xp);
    lstm_rec_tc<false><<<NCTA, RTHR, REC_SMEM>>>(xp, w21, bp1,
                                                 nullptr, nullptr, h2l);

    head_kernel<<<BATCH, HH>>>(h2l, ln_g, ln_b, hw, hb, outp);
}